// round 1
// baseline (speedup 1.0000x reference)
#include <cuda_runtime.h>

// ForceAggregation: out[m*D + r] = sum_j hess[m*D*D + r*D + j] * ns[m*D + j]
// M molecules, D = 3*N_AT degrees of freedom (D=300 for this dataset).
// Pure HBM-streaming batched matvec: hess (737 MB) read once, ns cached in SMEM.

#define ROWS_PER_BLOCK 64
#define BLOCK_THREADS 256

template <int D>
__global__ void __launch_bounds__(BLOCK_THREADS)
force_agg_kernel(const float* __restrict__ hess,
                 const float* __restrict__ ns,
                 float* __restrict__ out,
                 int tiles_per_mol)
{
    extern __shared__ __align__(16) float s_ns[];

    const int m    = blockIdx.x / tiles_per_mol;
    const int tile = blockIdx.x - m * tiles_per_mol;
    const int row0 = tile * ROWS_PER_BLOCK;

    // Stage ns_m (D floats = 1.2 KB) into shared memory once per block.
    const float* nsm = ns + (size_t)m * D;
    constexpr int NCH = D / 4;                 // full float4 chunks
    for (int i = threadIdx.x; i < NCH; i += BLOCK_THREADS)
        ((float4*)s_ns)[i] = ((const float4*)nsm)[i];
    if (D & 3) {
        for (int i = NCH * 4 + threadIdx.x; i < D; i += BLOCK_THREADS)
            s_ns[i] = nsm[i];
    }
    __syncthreads();

    const int warp  = threadIdx.x >> 5;
    const int lane  = threadIdx.x & 31;
    const int nwrps = BLOCK_THREADS >> 5;

    const float4* s4    = (const float4*)s_ns;
    const float*  hbase = hess + (size_t)m * D * D;

    int rend = row0 + ROWS_PER_BLOCK;
    if (rend > D) rend = D;

    for (int r = row0 + warp; r < rend; r += nwrps) {
        const float4* hrow = (const float4*)(hbase + (size_t)r * D);
        float acc = 0.0f;
#pragma unroll
        for (int k = 0; k < (NCH + 31) / 32; ++k) {
            const int c = lane + k * 32;
            if (c < NCH) {
                const float4 h = hrow[c];
                const float4 n = s4[c];
                acc = fmaf(h.x, n.x, acc);
                acc = fmaf(h.y, n.y, acc);
                acc = fmaf(h.z, n.z, acc);
                acc = fmaf(h.w, n.w, acc);
            }
        }
        if (D & 3) {
            const int c = NCH * 4 + lane;   // D%4 < 32 always
            if (c < D)
                acc = fmaf(hbase[(size_t)r * D + c], s_ns[c], acc);
        }
        // Warp reduction
#pragma unroll
        for (int off = 16; off; off >>= 1)
            acc += __shfl_xor_sync(0xffffffffu, acc, off);
        if (lane == 0)
            out[(size_t)m * D + r] = acc;
    }
}

// Generic fallback for unexpected D (runtime loop bounds).
__global__ void __launch_bounds__(BLOCK_THREADS)
force_agg_generic(const float* __restrict__ hess,
                  const float* __restrict__ ns,
                  float* __restrict__ out,
                  int D, int tiles_per_mol)
{
    extern __shared__ __align__(16) float s_ns[];

    const int m    = blockIdx.x / tiles_per_mol;
    const int tile = blockIdx.x - m * tiles_per_mol;
    const int row0 = tile * ROWS_PER_BLOCK;

    const float* nsm = ns + (size_t)m * D;
    const int nch = D >> 2;
    for (int i = threadIdx.x; i < nch; i += BLOCK_THREADS)
        ((float4*)s_ns)[i] = ((const float4*)nsm)[i];
    for (int i = nch * 4 + threadIdx.x; i < D; i += BLOCK_THREADS)
        s_ns[i] = nsm[i];
    __syncthreads();

    const int warp  = threadIdx.x >> 5;
    const int lane  = threadIdx.x & 31;
    const int nwrps = BLOCK_THREADS >> 5;

    const float4* s4    = (const float4*)s_ns;
    const float*  hbase = hess + (size_t)m * D * D;

    int rend = row0 + ROWS_PER_BLOCK;
    if (rend > D) rend = D;

    for (int r = row0 + warp; r < rend; r += nwrps) {
        const float4* hrow = (const float4*)(hbase + (size_t)r * D);
        float acc = 0.0f;
        for (int c = lane; c < nch; c += 32) {
            const float4 h = hrow[c];
            const float4 n = s4[c];
            acc = fmaf(h.x, n.x, acc);
            acc = fmaf(h.y, n.y, acc);
            acc = fmaf(h.z, n.z, acc);
            acc = fmaf(h.w, n.w, acc);
        }
        for (int c = nch * 4 + lane; c < D; c += 32)
            acc = fmaf(hbase[(size_t)r * D + c], s_ns[c], acc);
#pragma unroll
        for (int off = 16; off; off >>= 1)
            acc += __shfl_xor_sync(0xffffffffu, acc, off);
        if (lane == 0)
            out[(size_t)m * D + r] = acc;
    }
}

extern "C" void kernel_launch(void* const* d_in, const int* in_sizes, int n_in,
                              void* d_out, int out_size)
{
    // Input order (metadata): ns [M*N_AT,3] f32, hess [M*D,D] f32,
    //                         idx_m [M*N_AT] i32, n_atoms [M] i32
    const float* ns   = (const float*)d_in[0];
    const float* hess = (const float*)d_in[1];
    float*       out  = (float*)d_out;

    const int M = in_sizes[3];                      // n_atoms has one entry per molecule
    const int D = (int)((long long)in_sizes[0] / M); // ns has M*D elements (M*N_AT*3)

    const int tiles = (D + ROWS_PER_BLOCK - 1) / ROWS_PER_BLOCK;
    const dim3 grid((unsigned)(M * tiles));
    const dim3 block(BLOCK_THREADS);
    const size_t shmem = (size_t)((D + 3) / 4) * 16; // D floats, 16B-aligned

    if (D == 300) {
        force_agg_kernel<300><<<grid, block, shmem>>>(hess, ns, out, tiles);
    } else {
        force_agg_generic<<<grid, block, shmem>>>(hess, ns, out, D, tiles);
    }
}

// round 2
// speedup vs baseline: 1.0575x; 1.0575x over previous
#include <cuda_runtime.h>

// ForceAggregation: out[m*D + r] = dot(hess[m][r][:], ns[m][:]),  D=300, M=2048.
// Pure HBM stream (hess = 737 MB read once). Strategy:
//  - warp per row-pair, 6 independent __ldcs float4 loads front-batched (MLP=6)
//  - ns chunks hoisted to registers (identical for every row a lane touches)
//  - evict-first loads keep zero-reuse hess from thrashing L2
//  - paired float2 output stores

#define ROWS_PER_BLOCK 64
#define BLOCK_THREADS 256

__device__ __forceinline__ float dot4(float4 a, float4 b, float acc) {
    acc = fmaf(a.x, b.x, acc);
    acc = fmaf(a.y, b.y, acc);
    acc = fmaf(a.z, b.z, acc);
    return fmaf(a.w, b.w, acc);
}

template <int D>
__global__ void __launch_bounds__(BLOCK_THREADS)
force_agg_kernel(const float* __restrict__ hess,
                 const float* __restrict__ ns,
                 float* __restrict__ out,
                 int tiles_per_mol)
{
    const int m    = blockIdx.x / tiles_per_mol;
    const int tile = blockIdx.x - m * tiles_per_mol;
    const int row0 = tile * ROWS_PER_BLOCK;

    const int warp = threadIdx.x >> 5;
    const int lane = threadIdx.x & 31;

    constexpr int NCH = D / 4;                    // 75 float4 chunks per row
    constexpr int NIT = (NCH + 31) / 32;          // 3 lane-iterations
    static_assert(NIT == 3, "tuned for D in (256,384]");

    // Hoist this lane's ns chunks into registers — reused by every row.
    const float4* ns4 = (const float4*)(ns + (size_t)m * D);
    const float4  z4  = make_float4(0.f, 0.f, 0.f, 0.f);
    float4 n0 = __ldg(ns4 + lane);
    float4 n1 = __ldg(ns4 + lane + 32);
    float4 n2 = (lane < NCH - 64) ? __ldg(ns4 + lane + 64) : z4;

    const float* hbase = hess + (size_t)m * D * D;

    int rend = row0 + ROWS_PER_BLOCK;
    if (rend > D) rend = D;

    for (int r = row0 + (warp << 1); r < rend; r += 2 * (BLOCK_THREADS / 32)) {
        const bool two = (r + 1 < rend);
        const float4* h0 = (const float4*)(hbase + (size_t)r * D);
        const float4* h1 = (const float4*)(hbase + (size_t)(r + 1) * D);

        // Front-batch 6 independent streaming loads.
        float4 a0 = __ldcs(h0 + lane);
        float4 b0 = two ? __ldcs(h1 + lane) : z4;
        float4 a1 = __ldcs(h0 + lane + 32);
        float4 b1 = two ? __ldcs(h1 + lane + 32) : z4;
        float4 a2 = z4, b2 = z4;
        if (lane < NCH - 64) {
            a2 = __ldcs(h0 + lane + 64);
            if (two) b2 = __ldcs(h1 + lane + 64);
        }

        float acc0 = dot4(a0, n0, 0.f);
        float acc1 = dot4(b0, n0, 0.f);
        acc0 = dot4(a1, n1, acc0);
        acc1 = dot4(b1, n1, acc1);
        acc0 = dot4(a2, n2, acc0);
        acc1 = dot4(b2, n2, acc1);

#pragma unroll
        for (int off = 16; off; off >>= 1) {
            acc0 += __shfl_xor_sync(0xffffffffu, acc0, off);
            acc1 += __shfl_xor_sync(0xffffffffu, acc1, off);
        }
        if (lane == 0) {
            if (two) {
                // m*D + r is even (D even, r even) -> 8B aligned
                *(float2*)(out + (size_t)m * D + r) = make_float2(acc0, acc1);
            } else {
                out[(size_t)m * D + r] = acc0;
            }
        }
    }
}

// Generic fallback for unexpected D (runtime loop bounds, smem-staged ns).
__global__ void __launch_bounds__(BLOCK_THREADS)
force_agg_generic(const float* __restrict__ hess,
                  const float* __restrict__ ns,
                  float* __restrict__ out,
                  int D, int tiles_per_mol)
{
    extern __shared__ __align__(16) float s_ns[];

    const int m    = blockIdx.x / tiles_per_mol;
    const int tile = blockIdx.x - m * tiles_per_mol;
    const int row0 = tile * ROWS_PER_BLOCK;

    const float* nsm = ns + (size_t)m * D;
    const int nch = D >> 2;
    for (int i = threadIdx.x; i < nch; i += BLOCK_THREADS)
        ((float4*)s_ns)[i] = ((const float4*)nsm)[i];
    for (int i = nch * 4 + threadIdx.x; i < D; i += BLOCK_THREADS)
        s_ns[i] = nsm[i];
    __syncthreads();

    const int warp  = threadIdx.x >> 5;
    const int lane  = threadIdx.x & 31;
    const int nwrps = BLOCK_THREADS >> 5;

    const float4* s4    = (const float4*)s_ns;
    const float*  hbase = hess + (size_t)m * D * D;

    int rend = row0 + ROWS_PER_BLOCK;
    if (rend > D) rend = D;

    for (int r = row0 + warp; r < rend; r += nwrps) {
        const float4* hrow = (const float4*)(hbase + (size_t)r * D);
        float acc = 0.0f;
        for (int c = lane; c < nch; c += 32) {
            const float4 h = __ldcs(hrow + c);
            const float4 n = s4[c];
            acc = fmaf(h.x, n.x, acc);
            acc = fmaf(h.y, n.y, acc);
            acc = fmaf(h.z, n.z, acc);
            acc = fmaf(h.w, n.w, acc);
        }
        for (int c = nch * 4 + lane; c < D; c += 32)
            acc = fmaf(hbase[(size_t)r * D + c], s_ns[c], acc);
#pragma unroll
        for (int off = 16; off; off >>= 1)
            acc += __shfl_xor_sync(0xffffffffu, acc, off);
        if (lane == 0)
            out[(size_t)m * D + r] = acc;
    }
}

extern "C" void kernel_launch(void* const* d_in, const int* in_sizes, int n_in,
                              void* d_out, int out_size)
{
    // Input order: ns [M*N_AT,3] f32, hess [M*D,D] f32, idx_m i32, n_atoms [M] i32
    const float* ns   = (const float*)d_in[0];
    const float* hess = (const float*)d_in[1];
    float*       out  = (float*)d_out;

    const int M = in_sizes[3];
    const int D = (int)((long long)in_sizes[0] / M);

    const int tiles = (D + ROWS_PER_BLOCK - 1) / ROWS_PER_BLOCK;
    const dim3 grid((unsigned)(M * tiles));
    const dim3 block(BLOCK_THREADS);

    if (D == 300) {
        force_agg_kernel<300><<<grid, block>>>(hess, ns, out, tiles);
    } else {
        const size_t shmem = (size_t)((D + 3) / 4) * 16;
        force_agg_generic<<<grid, block, shmem>>>(hess, ns, out, D, tiles);
    }
}